// round 15
// baseline (speedup 1.0000x reference)
#include <cuda_runtime.h>
#include <cuda_fp16.h>
#include <cstdint>

// ---------------------------------------------------------------------------
// GroupedLinear: y[b, g*256+o] = sum_i x[b, g*256+i] * W[g,o,i] + bias[g,o]
// 16 independent GEMMs: M=8192, N=256, K=256, fp32 in/out.
//
// R13/R14: wall = tensor-busy + L1tex-busy (serialized phases inside one
// barrier-locked CTA). tf32 rounds showed 2 independent CTAs/SM overlap
// those phases. R15: fp16 + 2 CTAs/SM: tile 128x128, 256 thr, 97KB smem,
// <=128 regs (A-LDG split into two overlaid half-buffers). x re-read by the
// n-pair CTA hits L2. Persistent 304 CTAs, fused cvt, mma.m16n8k16.f16.
// ---------------------------------------------------------------------------

namespace gl {

constexpr int INF  = 4096;
constexpr int NG   = 16;
constexpr int GIN  = 256;          // K per group
constexpr int GOUT = 256;          // N per group
constexpr int MT   = 128;          // CTA M tile
constexpr int NT   = 128;          // CTA N tile (half group)
constexpr int KCH  = 64;           // K chunk: 64 halves = 128 B rows
constexpr int NCHUNK = 4;          // K chunks per tile
constexpr int TILES = 2048;        // 16 groups x 64 m-tiles x 2 n-tiles
constexpr int NCTA  = 304;         // 2 CTAs x 152 SMs (GB300)
constexpr int NTHREADS = 256;      // 8 warps, 2(M) x 4(N), warp tile 64x32

constexpr int A_BYTES = MT * KCH * 2;           // 16 KB per stage
constexpr int B_BYTES = NT * KCH * 2;           // 16 KB per stage
constexpr int STAGE_BYTES = A_BYTES + B_BYTES;  // 32 KB

constexpr int OFF_STAGE = 1024;
constexpr int SMEM_TOTAL = OFF_STAGE + 3 * STAGE_BYTES;  // 99328 B -> 2 CTA/SM

__device__ __forceinline__ uint32_t swz(uint32_t x) {
    return x ^ ((x >> 3) & 0x70);
}

__device__ __forceinline__ void cp16(uint32_t dst, const void* src) {
    asm volatile("cp.async.cg.shared.global [%0], [%1], 16;"
                 :: "r"(dst), "l"(src) : "memory");
}

__device__ __forceinline__ uint32_t smem_u32(const void* p) {
    uint32_t a;
    asm("{ .reg .u64 t; cvta.to.shared.u64 t, %1; cvt.u32.u64 %0, t; }"
        : "=r"(a) : "l"(p));
    return a;
}

__device__ __forceinline__ void ldsm4(uint32_t& r0, uint32_t& r1,
                                      uint32_t& r2, uint32_t& r3,
                                      uint32_t addr) {
    asm volatile("ldmatrix.sync.aligned.m8n8.x4.shared.b16 {%0,%1,%2,%3}, [%4];"
                 : "=r"(r0), "=r"(r1), "=r"(r2), "=r"(r3) : "r"(addr));
}

__device__ __forceinline__ void mma_f16(float* c,
                                        uint32_t a0, uint32_t a1,
                                        uint32_t a2, uint32_t a3,
                                        uint32_t b0, uint32_t b1) {
    asm volatile(
        "mma.sync.aligned.m16n8k16.row.col.f32.f16.f16.f32 "
        "{%0,%1,%2,%3}, {%4,%5,%6,%7}, {%8,%9}, {%0,%1,%2,%3};"
        : "+f"(c[0]), "+f"(c[1]), "+f"(c[2]), "+f"(c[3])
        : "r"(a0), "r"(a1), "r"(a2), "r"(a3), "r"(b0), "r"(b1));
}

__device__ __forceinline__ uint32_t h2u(__half2 h) {
    return *reinterpret_cast<uint32_t*>(&h);
}

} // namespace gl

using namespace gl;

// fp16 copy of W (2MB), produced once per launch (idempotent, deterministic).
__device__ __half g_Wh[NG * GOUT * GIN];

__global__ __launch_bounds__(256, 8)
void GroupedLinear_cvtW_kernel(const float4* __restrict__ in,
                               uint2* __restrict__ out, int n4) {
    const int stride = gridDim.x * 256;
    for (int i = blockIdx.x * 256 + threadIdx.x; i < n4; i += stride) {
        float4 v = in[i];
        __half2 lo = __floats2half2_rn(v.x, v.y);
        __half2 hi = __floats2half2_rn(v.z, v.w);
        uint2 o;
        o.x = *reinterpret_cast<uint32_t*>(&lo);
        o.y = *reinterpret_cast<uint32_t*>(&hi);
        out[i] = o;
    }
}

__global__ __launch_bounds__(NTHREADS, 2)
void GroupedLinear_35364760715975_kernel(const float* __restrict__ x,
                                         const float* __restrict__ bias,
                                         float* __restrict__ y)
{
    extern __shared__ char smem[];
    const uint32_t sbase = smem_u32(smem);
    const int tid = threadIdx.x;
    const int bid = blockIdx.x;

    // ---- A loader: 2 threads per row; thread covers 128B fp32 (32 floats)
    const int arr = tid >> 1;        // row 0..127
    const int ach = tid & 1;         // 128B half of the 256B fp32 row
    uint32_t astso[4];               // fp16 16B slots (64B per thread)
    #pragma unroll
    for (int j = 0; j < 4; j++)
        astso[j] = swz((uint32_t)(arr * 128 + ach * 64 + j * 16));

    // half-chunk register buffers (disjoint liveness -> overlaid by ptxas)
    float4 abuf1[4], abuf2[4];

    auto ldgA = [&](int q, int half, float4* bp) {
        const int tile = bid + (q >> 2) * NCTA;
        const int g    = tile >> 7;
        const int mt   = (tile & 127) >> 1;
        const float4* p = (const float4*)(x + (size_t)(mt * MT + arr) * INF
                              + g * GIN + (q & 3) * KCH + ach * 32 + half * 16);
        #pragma unroll
        for (int i = 0; i < 4; i++) bp[i] = p[i];
    };

    auto stsA = [&](int buf, int half, const float4* bp) {
        const uint32_t ab = sbase + OFF_STAGE + buf * STAGE_BYTES;
        #pragma unroll
        for (int j = 0; j < 2; j++) {
            uint32_t h0 = h2u(__floats2half2_rn(bp[2*j].x,   bp[2*j].y));
            uint32_t h1 = h2u(__floats2half2_rn(bp[2*j].z,   bp[2*j].w));
            uint32_t h2 = h2u(__floats2half2_rn(bp[2*j+1].x, bp[2*j+1].y));
            uint32_t h3 = h2u(__floats2half2_rn(bp[2*j+1].z, bp[2*j+1].w));
            asm volatile("st.shared.v4.b32 [%0], {%1,%2,%3,%4};"
                         :: "r"(ab + astso[half * 2 + j]),
                            "r"(h0), "r"(h1), "r"(h2), "r"(h3) : "memory");
        }
    };

    // ---- B loader (cp.async from g_Wh): 2 threads per 128B row ----
    uint32_t dstoB[4];
    #pragma unroll
    for (int j = 0; j < 4; j++)
        dstoB[j] = swz((uint32_t)(arr * 128 + ach * 64 + j * 16));

    auto loadB = [&](int q, int buf) {
        const int tile = bid + (q >> 2) * NCTA;
        const int g    = tile >> 7;
        const int ntl  = tile & 1;
        const __half* ws = g_Wh + (size_t)(g * GOUT + ntl * NT + arr) * GIN
                                + (q & 3) * KCH + ach * 32;
        const uint32_t bbase = sbase + OFF_STAGE + buf * STAGE_BYTES + A_BYTES;
        #pragma unroll
        for (int j = 0; j < 4; j++)
            cp16(bbase + dstoB[j], ws + j * 8);
    };

    const int ntiles = (TILES - 1 - bid) / NCTA + 1;
    const int qtot = ntiles * NCHUNK;

    // ---- prologue: A(0) fully, A1(1) staged, A2(1) in regs; B(0), B(1) ----
    ldgA(0, 0, abuf1);
    ldgA(0, 1, abuf2);
    stsA(0, 0, abuf1);
    stsA(0, 1, abuf2);
    loadB(0, 0); asm volatile("cp.async.commit_group;" ::: "memory");
    ldgA(1, 0, abuf1);
    stsA(1, 0, abuf1);
    ldgA(1, 1, abuf2);              // held in regs into iter 0
    loadB(1, 1); asm volatile("cp.async.commit_group;" ::: "memory");

    // ---- per-warp geometry: 2(M) x 4(N) warps, warp tile 64x32 ----
    const int wid  = tid >> 5;
    const int lane = tid & 31;
    const int wm = wid >> 2;          // 0..1
    const int wn = wid & 3;           // 0..3
    const int grp = lane >> 2;        // 0..7
    const int tig = lane & 3;         // 0..3
    const int kk0 = wid & 3;          // stagger k-step order per warp

    // ldmatrix lane geometry (b16, canonical m16n8k16 fragments)
    const int q8 = lane >> 3;         // 0..3
    const int i8 = lane & 7;          // 0..7
    const uint32_t ix = (uint32_t)i8 << 4;
    const uint32_t aq16 = (uint32_t)((q8 >> 1) << 4);
    const uint32_t arow = (uint32_t)(((q8 & 1) * 8 + i8) * 128) + (uint32_t)(wm << 13);
    const uint32_t bq16 = (uint32_t)((q8 & 1) << 4);
    const uint32_t brow = (uint32_t)(((q8 >> 1) * 8 + i8) * 128) + (uint32_t)(wn << 12);

    float acc[4][4][4];               // 64 regs
    #pragma unroll
    for (int a = 0; a < 4; a++)
        #pragma unroll
        for (int b = 0; b < 4; b++)
            #pragma unroll
            for (int c = 0; c < 4; c++) acc[a][b][c] = 0.f;

    // ---- flat persistent mainloop over (tile, k64-chunk) ----
    int buf = 0;                      // q % 3
    #pragma unroll 1
    for (int q = 0; q < qtot; q++) {
        asm volatile("cp.async.wait_group 1;" ::: "memory");
        __syncthreads();   // stage q visible; buffer (q+2)%3 reader-free

        const int bufn1 = (buf == 2) ? 0 : buf + 1;     // (q+1)%3
        const int bufn2 = (buf == 0) ? 2 : buf - 1;     // (q+2)%3

        if (q + 1 < qtot) stsA(bufn1, 1, abuf2);        // finish A(q+1)
        if (q + 2 < qtot) {
            ldgA(q + 2, 0, abuf1);
            loadB(q + 2, bufn2);
            asm volatile("cp.async.commit_group;" ::: "memory");
        } else {
            asm volatile("cp.async.commit_group;" ::: "memory");
        }

        const uint32_t stage = sbase + OFF_STAGE + buf * STAGE_BYTES;
        const uint32_t Arow = stage + arow;
        const uint32_t Brow = stage + A_BYTES + brow;

        #pragma unroll
        for (int j = 0; j < 4; j++) {
            const int kk = (j + kk0) & 3;
            const uint32_t cxA = ((uint32_t)(kk * 32) + aq16) ^ ix;
            const uint32_t cxB = ((uint32_t)(kk * 32) + bq16) ^ ix;

            uint32_t af[4][4];
            #pragma unroll
            for (int mti = 0; mti < 4; mti++)
                ldsm4(af[mti][0], af[mti][1], af[mti][2], af[mti][3],
                      Arow + (uint32_t)(mti * 2048) + cxA);

            uint32_t bf[4][2];
            ldsm4(bf[0][0], bf[0][1], bf[1][0], bf[1][1], Brow + cxB);
            ldsm4(bf[2][0], bf[2][1], bf[3][0], bf[3][1], Brow + 2048u + cxB);

            #pragma unroll
            for (int mti = 0; mti < 4; mti++)
                #pragma unroll
                for (int nti = 0; nti < 4; nti++)
                    mma_f16(acc[mti][nti],
                            af[mti][0], af[mti][1], af[mti][2], af[mti][3],
                            bf[nti][0], bf[nti][1]);

            if (j == 1 && q + 2 < qtot) {
                stsA(bufn2, 0, abuf1);       // first half of A(q+2)
                ldgA(q + 2, 1, abuf2);       // held into iter q+1
            }
        }

        // ---- tile boundary: barrier-free inline epilogue ----
        if ((q & 3) == 3) {
            const int tile = bid + (q >> 2) * NCTA;
            const int g    = tile >> 7;
            const int rem  = tile & 127;
            const int m0   = (rem >> 1) * MT;
            const int n0   = (rem & 1) * NT;
            const int col0 = g * GOUT + n0 + wn * 32 + tig * 2;

            const float* bp = bias + col0;
            float2 bv[4];
            #pragma unroll
            for (int nti = 0; nti < 4; nti++)
                bv[nti] = *(const float2*)(bp + nti * 8);

            #pragma unroll
            for (int mti = 0; mti < 4; mti++) {
                const int row0 = m0 + wm * 64 + mti * 16 + grp;
                float* yr0 = y + (size_t)row0 * INF + col0;
                float* yr1 = yr0 + (size_t)8 * INF;
                #pragma unroll
                for (int nti = 0; nti < 4; nti++) {
                    float2 v0, v1;
                    v0.x = acc[mti][nti][0] + bv[nti].x;
                    v0.y = acc[mti][nti][1] + bv[nti].y;
                    v1.x = acc[mti][nti][2] + bv[nti].x;
                    v1.y = acc[mti][nti][3] + bv[nti].y;
                    *(float2*)(yr0 + nti * 8) = v0;
                    *(float2*)(yr1 + nti * 8) = v1;
                    acc[mti][nti][0] = 0.f; acc[mti][nti][1] = 0.f;
                    acc[mti][nti][2] = 0.f; acc[mti][nti][3] = 0.f;
                }
            }
        }

        buf = bufn1;
    }
}

extern "C" void kernel_launch(void* const* d_in, const int* in_sizes, int n_in,
                              void* d_out, int out_size) {
    const float* x  = (const float*)d_in[0];
    const float* Wt = (const float*)d_in[1];
    const float* b  = (const float*)d_in[2];
    float* y = (float*)d_out;

    cudaFuncSetAttribute(GroupedLinear_35364760715975_kernel,
                         cudaFuncAttributeMaxDynamicSharedMemorySize, SMEM_TOTAL);

    // 1) convert W (1M f32) to fp16 rne (~1us)
    __half* wh_dev = nullptr;
    cudaGetSymbolAddress((void**)&wh_dev, g_Wh);
    GroupedLinear_cvtW_kernel<<<256, 256>>>((const float4*)Wt,
                                            (uint2*)wh_dev, NG * GOUT * GIN / 4);

    // 2) persistent fused cvt+GEMM: 304 CTAs (2 per SM on 152-SM GB300)
    GroupedLinear_35364760715975_kernel<<<NCTA, NTHREADS, SMEM_TOTAL>>>(x, b, y);
}

// round 16
// speedup vs baseline: 2.0930x; 2.0930x over previous
#include <cuda_runtime.h>
#include <cuda_fp16.h>
#include <cstdint>

// ---------------------------------------------------------------------------
// GroupedLinear: y[b, g*256+o] = sum_i x[b, g*256+i] * W[g,o,i] + bias[g,o]
// 16 independent GEMMs: M=8192, N=256, K=256, fp32 in/out.
//
// R15 regressed (184us): loader lane remap broke sector-perfectness + STS
// bank conflicts. R16: decorrelation done right — ONE 512-thread CTA holding
// TWO independent 256-thread pipelines (own tiles, own 3-stage smem rings,
// named barriers). All loader/fragment geometry identical to proven R13.
// fp16 mma.m16n8k16, fused x conversion, W-fp16 prepass, persistent CTAs.
// ---------------------------------------------------------------------------

namespace gl {

constexpr int INF  = 4096;
constexpr int NG   = 16;
constexpr int GIN  = 256;
constexpr int GOUT = 256;
constexpr int MT   = 128;          // per-pipeline M tile
constexpr int NT   = 128;          // per-pipeline N tile (half group)
constexpr int KCH  = 64;           // 64 halves = 128B fp16 rows
constexpr int NCHUNK = 4;
constexpr int TILES = 2048;        // 16 g x 64 mt x 2 nt
constexpr int NCTA  = 152;         // 1 CTA/SM
constexpr int NWORK = 304;         // 2 pipelines per CTA
constexpr int NTHREADS = 512;

constexpr int A_BYTES = MT * KCH * 2;           // 16 KB
constexpr int B_BYTES = NT * KCH * 2;           // 16 KB
constexpr int STAGE_BYTES = A_BYTES + B_BYTES;  // 32 KB
constexpr int RING_BYTES = 3 * STAGE_BYTES;     // 96 KB per pipeline

constexpr int OFF_STAGE = 1024;
constexpr int SMEM_TOTAL = OFF_STAGE + 2 * RING_BYTES;  // 197632 B -> 1 CTA/SM

__device__ __forceinline__ uint32_t swz(uint32_t x) {
    return x ^ ((x >> 3) & 0x70);
}

__device__ __forceinline__ void cp16(uint32_t dst, const void* src) {
    asm volatile("cp.async.cg.shared.global [%0], [%1], 16;"
                 :: "r"(dst), "l"(src) : "memory");
}

__device__ __forceinline__ uint32_t smem_u32(const void* p) {
    uint32_t a;
    asm("{ .reg .u64 t; cvta.to.shared.u64 t, %1; cvt.u32.u64 %0, t; }"
        : "=r"(a) : "l"(p));
    return a;
}

__device__ __forceinline__ void ldsm4(uint32_t& r0, uint32_t& r1,
                                      uint32_t& r2, uint32_t& r3,
                                      uint32_t addr) {
    asm volatile("ldmatrix.sync.aligned.m8n8.x4.shared.b16 {%0,%1,%2,%3}, [%4];"
                 : "=r"(r0), "=r"(r1), "=r"(r2), "=r"(r3) : "r"(addr));
}

__device__ __forceinline__ void mma_f16(float* c,
                                        uint32_t a0, uint32_t a1,
                                        uint32_t a2, uint32_t a3,
                                        uint32_t b0, uint32_t b1) {
    asm volatile(
        "mma.sync.aligned.m16n8k16.row.col.f32.f16.f16.f32 "
        "{%0,%1,%2,%3}, {%4,%5,%6,%7}, {%8,%9}, {%0,%1,%2,%3};"
        : "+f"(c[0]), "+f"(c[1]), "+f"(c[2]), "+f"(c[3])
        : "r"(a0), "r"(a1), "r"(a2), "r"(a3), "r"(b0), "r"(b1));
}

__device__ __forceinline__ uint32_t h2u(__half2 h) {
    return *reinterpret_cast<uint32_t*>(&h);
}

} // namespace gl

using namespace gl;

// fp16 copy of W (2MB), produced once per launch (idempotent, deterministic).
__device__ __half g_Wh[NG * GOUT * GIN];

__global__ __launch_bounds__(256, 8)
void GroupedLinear_cvtW_kernel(const float4* __restrict__ in,
                               uint2* __restrict__ out, int n4) {
    const int stride = gridDim.x * 256;
    for (int i = blockIdx.x * 256 + threadIdx.x; i < n4; i += stride) {
        float4 v = in[i];
        __half2 lo = __floats2half2_rn(v.x, v.y);
        __half2 hi = __floats2half2_rn(v.z, v.w);
        uint2 o;
        o.x = *reinterpret_cast<uint32_t*>(&lo);
        o.y = *reinterpret_cast<uint32_t*>(&hi);
        out[i] = o;
    }
}

__global__ __launch_bounds__(NTHREADS, 1)
void GroupedLinear_35364760715975_kernel(const float* __restrict__ x,
                                         const float* __restrict__ bias,
                                         float* __restrict__ y)
{
    extern __shared__ char smem[];
    const uint32_t sbase = smem_u32(smem);
    const int tid = threadIdx.x;
    const int grp = tid >> 8;           // pipeline 0/1
    const int tg  = tid & 255;          // thread within pipeline
    const int worker = blockIdx.x * 2 + grp;   // 0..303
    const uint32_t ring = sbase + OFF_STAGE + (uint32_t)grp * RING_BYTES;
    const int barid = 1 + grp;

    // ---- loader lane geometry (PROVEN R13 mapping, per 256-thr group) ----
    const int lrr = tg >> 3;        // row 0..31 (+32 per iter)
    const int lss = tg & 7;         // 32B fp32 slot == 16B fp16 slot

    uint32_t sto[4];                // swizzled dst for rows lrr+32i
    #pragma unroll
    for (int i = 0; i < 4; i++)
        sto[i] = swz((uint32_t)((lrr + i * 32) * 128 + lss * 16));

    // B loader: cp.async from g_Wh, 4 iters x 32 rows = 128 rows
    auto loadB = [&](int q, int buf) {
        const int tile = worker + (q >> 2) * NWORK;
        const int g    = tile >> 7;
        const int ntl  = tile & 1;
        const __half* ws = g_Wh + (size_t)(g * GOUT + ntl * NT + lrr) * GIN
                                + (q & 3) * KCH + lss * 8;
        const uint32_t bb = ring + buf * STAGE_BYTES + A_BYTES;
        #pragma unroll
        for (int i = 0; i < 4; i++)
            cp16(bb + sto[i], ws + (size_t)(i * 32) * GIN);
    };

    // A loader: sector-perfect LDG fp32 (8 contiguous floats per thread),
    // split into two half-buffers: half h covers rows lrr+32*(2h), lrr+32*(2h+1)
    float4 abuf1[4], abuf2[4];

    auto ldgA = [&](int q, int h, float4* bp) {
        const int tile = worker + (q >> 2) * NWORK;
        const int g    = tile >> 7;
        const int mt   = (tile & 127) >> 1;
        const float* base = x + (size_t)(mt * MT + lrr + 64 * h) * INF
                              + g * GIN + (q & 3) * KCH + lss * 8;
        #pragma unroll
        for (int i = 0; i < 2; i++) {
            const float4* p = (const float4*)(base + (size_t)(i * 32) * INF);
            bp[2 * i]     = p[0];
            bp[2 * i + 1] = p[1];
        }
    };

    auto stsA = [&](int buf, int h, const float4* bp) {
        const uint32_t ab = ring + buf * STAGE_BYTES;
        #pragma unroll
        for (int i = 0; i < 2; i++) {
            uint32_t h0 = h2u(__floats2half2_rn(bp[2*i].x,   bp[2*i].y));
            uint32_t h1 = h2u(__floats2half2_rn(bp[2*i].z,   bp[2*i].w));
            uint32_t h2 = h2u(__floats2half2_rn(bp[2*i+1].x, bp[2*i+1].y));
            uint32_t h3 = h2u(__floats2half2_rn(bp[2*i+1].z, bp[2*i+1].w));
            asm volatile("st.shared.v4.b32 [%0], {%1,%2,%3,%4};"
                         :: "r"(ab + sto[2 * h + i]),
                            "r"(h0), "r"(h1), "r"(h2), "r"(h3) : "memory");
        }
    };

    const int ntiles = (TILES - 1 - worker) / NWORK + 1;
    const int qtot = ntiles * NCHUNK;

    // ---- prologue: fully stage chunks 0 and 1 ----
    ldgA(0, 0, abuf1); ldgA(0, 1, abuf2);
    stsA(0, 0, abuf1); stsA(0, 1, abuf2);
    loadB(0, 0); asm volatile("cp.async.commit_group;" ::: "memory");
    ldgA(1, 0, abuf1); ldgA(1, 1, abuf2);
    stsA(1, 0, abuf1); stsA(1, 1, abuf2);
    loadB(1, 1); asm volatile("cp.async.commit_group;" ::: "memory");

    // ---- per-warp geometry within group: 2(M) x 4(N), warp tile 64x32 ----
    const int wid  = tg >> 5;
    const int lane = tg & 31;
    const int wm = wid >> 2;
    const int wn = wid & 3;
    const int grow8 = lane >> 2;      // 0..7
    const int tig = lane & 3;
    const int kk0 = wid & 3;

    const int q8 = lane >> 3;
    const int i8 = lane & 7;
    const uint32_t ix = (uint32_t)i8 << 4;
    const uint32_t aq16 = (uint32_t)((q8 >> 1) << 4);
    const uint32_t arow = (uint32_t)(((q8 & 1) * 8 + i8) * 128) + (uint32_t)(wm << 13);
    const uint32_t bq16 = (uint32_t)((q8 & 1) << 4);
    const uint32_t brow = (uint32_t)(((q8 >> 1) * 8 + i8) * 128) + (uint32_t)(wn << 12);

    float acc[4][4][4];               // 64 regs
    #pragma unroll
    for (int a = 0; a < 4; a++)
        #pragma unroll
        for (int b = 0; b < 4; b++)
            #pragma unroll
            for (int c = 0; c < 4; c++) acc[a][b][c] = 0.f;

    // ---- flat persistent mainloop (group-independent) ----
    int buf = 0;
    #pragma unroll 1
    for (int q = 0; q < qtot; q++) {
        asm volatile("cp.async.wait_group 1;" ::: "memory");
        asm volatile("bar.sync %0, 256;" :: "r"(barid) : "memory");

        const int bufn2 = (buf == 0) ? 2 : buf - 1;     // (q+2)%3
        const bool more = (q + 2 < qtot);

        if (more) {
            ldgA(q + 2, 0, abuf1);
            loadB(q + 2, bufn2);
            asm volatile("cp.async.commit_group;" ::: "memory");
        } else {
            asm volatile("cp.async.commit_group;" ::: "memory");
        }

        const uint32_t stage = ring + buf * STAGE_BYTES;
        const uint32_t Arow = stage + arow;
        const uint32_t Brow = stage + A_BYTES + brow;

        #pragma unroll
        for (int j = 0; j < 4; j++) {
            const int kk = (j + kk0) & 3;
            const uint32_t cxA = ((uint32_t)(kk * 32) + aq16) ^ ix;
            const uint32_t cxB = ((uint32_t)(kk * 32) + bq16) ^ ix;

            uint32_t af[4][4];
            #pragma unroll
            for (int mti = 0; mti < 4; mti++)
                ldsm4(af[mti][0], af[mti][1], af[mti][2], af[mti][3],
                      Arow + (uint32_t)(mti * 2048) + cxA);

            uint32_t bf[4][2];
            ldsm4(bf[0][0], bf[0][1], bf[1][0], bf[1][1], Brow + cxB);
            ldsm4(bf[2][0], bf[2][1], bf[3][0], bf[3][1], Brow + 2048u + cxB);

            #pragma unroll
            for (int mti = 0; mti < 4; mti++)
                #pragma unroll
                for (int nti = 0; nti < 4; nti++)
                    mma_f16(acc[mti][nti],
                            af[mti][0], af[mti][1], af[mti][2], af[mti][3],
                            bf[nti][0], bf[nti][1]);

            if (j == 1 && more) {
                stsA(bufn2, 0, abuf1);      // first half of A(q+2)
                ldgA(q + 2, 1, abuf2);
            }
            if (j == 3 && more) {
                stsA(bufn2, 1, abuf2);      // second half of A(q+2)
            }
        }

        // ---- tile boundary: barrier-free inline epilogue ----
        if ((q & 3) == 3) {
            const int tile = worker + (q >> 2) * NWORK;
            const int g    = tile >> 7;
            const int rem  = tile & 127;
            const int m0   = (rem >> 1) * MT;
            const int n0   = (rem & 1) * NT;
            const int col0 = g * GOUT + n0 + wn * 32 + tig * 2;

            const float* bp = bias + col0;
            float2 bv[4];
            #pragma unroll
            for (int nti = 0; nti < 4; nti++)
                bv[nti] = *(const float2*)(bp + nti * 8);

            #pragma unroll
            for (int mti = 0; mti < 4; mti++) {
                const int row0 = m0 + wm * 64 + mti * 16 + grow8;
                float* yr0 = y + (size_t)row0 * INF + col0;
                float* yr1 = yr0 + (size_t)8 * INF;
                #pragma unroll
                for (int nti = 0; nti < 4; nti++) {
                    float2 v0, v1;
                    v0.x = acc[mti][nti][0] + bv[nti].x;
                    v0.y = acc[mti][nti][1] + bv[nti].y;
                    v1.x = acc[mti][nti][2] + bv[nti].x;
                    v1.y = acc[mti][nti][3] + bv[nti].y;
                    *(float2*)(yr0 + nti * 8) = v0;
                    *(float2*)(yr1 + nti * 8) = v1;
                    acc[mti][nti][0] = 0.f; acc[mti][nti][1] = 0.f;
                    acc[mti][nti][2] = 0.f; acc[mti][nti][3] = 0.f;
                }
            }
        }

        buf = (buf == 2) ? 0 : buf + 1;
    }
}

extern "C" void kernel_launch(void* const* d_in, const int* in_sizes, int n_in,
                              void* d_out, int out_size) {
    const float* x  = (const float*)d_in[0];
    const float* Wt = (const float*)d_in[1];
    const float* b  = (const float*)d_in[2];
    float* y = (float*)d_out;

    cudaFuncSetAttribute(GroupedLinear_35364760715975_kernel,
                         cudaFuncAttributeMaxDynamicSharedMemorySize, SMEM_TOTAL);

    // 1) convert W (1M f32) to fp16 rne (~1us)
    __half* wh_dev = nullptr;
    cudaGetSymbolAddress((void**)&wh_dev, g_Wh);
    GroupedLinear_cvtW_kernel<<<256, 256>>>((const float4*)Wt,
                                            (uint2*)wh_dev, NG * GOUT * GIN / 4);

    // 2) persistent fused cvt+GEMM: 152 CTAs, 2 independent pipelines each
    GroupedLinear_35364760715975_kernel<<<NCTA, NTHREADS, SMEM_TOTAL>>>(x, b, y);
}

// round 17
// speedup vs baseline: 2.4742x; 1.1821x over previous
#include <cuda_runtime.h>
#include <cuda_fp16.h>
#include <cstdint>

// ---------------------------------------------------------------------------
// GroupedLinear: y[b, g*256+o] = sum_i x[b, g*256+i] * W[g,o,i] + bias[g,o]
// 16 independent GEMMs: M=8192, N=256, K=256, fp32 in/out.
//
// R13 best (72.4us): tensor 41% + L1tex 56% ~= 97% -> pipes SERIALIZED by
// the L1tex wavefront FIFO: prefetch wf (LDG/STS/cp ~640) issue before the
// chunk's LDSMs, delaying all MMAs. R17: same kernel, FIFO-aware order:
// LDSM(k0,k1) first after barrier, then prefetch, then pipelined
// MMA/LDSM tail. Everything else identical to R13.
// ---------------------------------------------------------------------------

namespace gl {

constexpr int INF  = 4096;
constexpr int NG   = 16;
constexpr int GIN  = 256;
constexpr int GOUT = 256;
constexpr int MT   = 128;          // CTA M tile
constexpr int NT   = 256;          // CTA N tile (full group)
constexpr int KCH  = 64;           // 64 halves = 128B fp16 rows
constexpr int NCHUNK = 4;
constexpr int TILES = 1024;        // 16 g x 64 mt
constexpr int NCTA  = 152;         // 1 CTA/SM
constexpr int NTHREADS = 256;      // 8 warps, 2(M) x 4(N), warp tile 64x64

constexpr int A_BYTES = MT * KCH * 2;           // 16 KB
constexpr int B_BYTES = NT * KCH * 2;           // 32 KB
constexpr int STAGE_BYTES = A_BYTES + B_BYTES;  // 48 KB

constexpr int OFF_STAGE = 1024;
constexpr int SMEM_TOTAL = OFF_STAGE + 3 * STAGE_BYTES;  // 148480 B

__device__ __forceinline__ uint32_t swz(uint32_t x) {
    return x ^ ((x >> 3) & 0x70);
}

__device__ __forceinline__ void cp16(uint32_t dst, const void* src) {
    asm volatile("cp.async.cg.shared.global [%0], [%1], 16;"
                 :: "r"(dst), "l"(src) : "memory");
}

__device__ __forceinline__ uint32_t smem_u32(const void* p) {
    uint32_t a;
    asm("{ .reg .u64 t; cvta.to.shared.u64 t, %1; cvt.u32.u64 %0, t; }"
        : "=r"(a) : "l"(p));
    return a;
}

__device__ __forceinline__ void ldsm4(uint32_t& r0, uint32_t& r1,
                                      uint32_t& r2, uint32_t& r3,
                                      uint32_t addr) {
    asm volatile("ldmatrix.sync.aligned.m8n8.x4.shared.b16 {%0,%1,%2,%3}, [%4];"
                 : "=r"(r0), "=r"(r1), "=r"(r2), "=r"(r3) : "r"(addr));
}

__device__ __forceinline__ void mma_f16(float* c,
                                        uint32_t a0, uint32_t a1,
                                        uint32_t a2, uint32_t a3,
                                        uint32_t b0, uint32_t b1) {
    asm volatile(
        "mma.sync.aligned.m16n8k16.row.col.f32.f16.f16.f32 "
        "{%0,%1,%2,%3}, {%4,%5,%6,%7}, {%8,%9}, {%0,%1,%2,%3};"
        : "+f"(c[0]), "+f"(c[1]), "+f"(c[2]), "+f"(c[3])
        : "r"(a0), "r"(a1), "r"(a2), "r"(a3), "r"(b0), "r"(b1));
}

__device__ __forceinline__ uint32_t h2u(__half2 h) {
    return *reinterpret_cast<uint32_t*>(&h);
}

} // namespace gl

using namespace gl;

// fp16 copy of W (2MB), produced once per launch (idempotent, deterministic).
__device__ __half g_Wh[NG * GOUT * GIN];

__global__ __launch_bounds__(256, 8)
void GroupedLinear_cvtW_kernel(const float4* __restrict__ in,
                               uint2* __restrict__ out, int n4) {
    const int stride = gridDim.x * 256;
    for (int i = blockIdx.x * 256 + threadIdx.x; i < n4; i += stride) {
        float4 v = in[i];
        __half2 lo = __floats2half2_rn(v.x, v.y);
        __half2 hi = __floats2half2_rn(v.z, v.w);
        uint2 o;
        o.x = *reinterpret_cast<uint32_t*>(&lo);
        o.y = *reinterpret_cast<uint32_t*>(&hi);
        out[i] = o;
    }
}

__global__ __launch_bounds__(NTHREADS, 1)
void GroupedLinear_35364760715975_kernel(const float* __restrict__ x,
                                         const float* __restrict__ bias,
                                         float* __restrict__ y)
{
    extern __shared__ char smem[];
    const uint32_t sbase = smem_u32(smem);
    const int tid = threadIdx.x;
    const int bid = blockIdx.x;

    // ---- loader lane geometry (PROVEN R13 mapping) ----
    const int lrr = tid >> 3;        // row 0..31, +32 per iter
    const int lss = tid & 7;         // 32B fp32 slot == 16B fp16 slot

    uint32_t sto[4];
    #pragma unroll
    for (int i = 0; i < 4; i++)
        sto[i] = swz((uint32_t)((lrr + i * 32) * 128 + lss * 16));
    uint32_t stoB2[4];
    #pragma unroll
    for (int i = 0; i < 4; i++)
        stoB2[i] = swz((uint32_t)((lrr + 128 + i * 32) * 128 + lss * 16));

    // B loader: cp.async from g_Wh, 8 x 32 rows = 256 rows
    auto loadB = [&](int q, int buf) {
        const int g = (bid + (q >> 2) * NCTA) >> 6;
        const __half* ws = g_Wh + (size_t)(g * GOUT + lrr) * GIN
                                + (q & 3) * KCH + lss * 8;
        const uint32_t bb = sbase + OFF_STAGE + buf * STAGE_BYTES + A_BYTES;
        #pragma unroll
        for (int i = 0; i < 4; i++)
            cp16(bb + sto[i], ws + (size_t)(i * 32) * GIN);
        #pragma unroll
        for (int i = 0; i < 4; i++)
            cp16(bb + stoB2[i], ws + (size_t)((i + 4) * 32) * GIN);
    };

    // A loader: sector-perfect LDG fp32 (8 contiguous floats per thread)
    float4 ldgbuf[8];                // 4 rows x 2 float4

    auto ldgA = [&](int q) {
        const int tile = bid + (q >> 2) * NCTA;
        const int g    = tile >> 6;
        const int mt   = tile & 63;
        const float* base = x + (size_t)(mt * MT + lrr) * INF
                              + g * GIN + (q & 3) * KCH + lss * 8;
        #pragma unroll
        for (int i = 0; i < 4; i++) {
            const float4* p = (const float4*)(base + (size_t)(i * 32) * INF);
            ldgbuf[2 * i]     = p[0];
            ldgbuf[2 * i + 1] = p[1];
        }
    };

    auto stsA = [&](int buf) {
        const uint32_t ab = sbase + OFF_STAGE + buf * STAGE_BYTES;
        #pragma unroll
        for (int i = 0; i < 4; i++) {
            uint32_t h0 = h2u(__floats2half2_rn(ldgbuf[2*i].x,   ldgbuf[2*i].y));
            uint32_t h1 = h2u(__floats2half2_rn(ldgbuf[2*i].z,   ldgbuf[2*i].w));
            uint32_t h2 = h2u(__floats2half2_rn(ldgbuf[2*i+1].x, ldgbuf[2*i+1].y));
            uint32_t h3 = h2u(__floats2half2_rn(ldgbuf[2*i+1].z, ldgbuf[2*i+1].w));
            asm volatile("st.shared.v4.b32 [%0], {%1,%2,%3,%4};"
                         :: "r"(ab + sto[i]), "r"(h0), "r"(h1), "r"(h2), "r"(h3)
                         : "memory");
        }
    };

    const int ntiles = (TILES - 1 - bid) / NCTA + 1;
    const int qtot = ntiles * NCHUNK;

    // ---- prologue ----
    ldgA(0);
    stsA(0);
    loadB(0, 0); asm volatile("cp.async.commit_group;" ::: "memory");
    ldgA(1);
    loadB(1, 1); asm volatile("cp.async.commit_group;" ::: "memory");

    // ---- per-warp geometry: 2(M) x 4(N), warp tile 64x64 ----
    const int wid  = tid >> 5;
    const int lane = tid & 31;
    const int wm = wid >> 2;
    const int wn = wid & 3;
    const int grp = lane >> 2;
    const int tig = lane & 3;
    const int kk0 = wid & 3;

    const int q8 = lane >> 3;
    const int i8 = lane & 7;
    const uint32_t ix = (uint32_t)i8 << 4;
    const uint32_t aq16 = (uint32_t)((q8 >> 1) << 4);
    const uint32_t arow = (uint32_t)(((q8 & 1) * 8 + i8) * 128) + (uint32_t)(wm << 13);
    const uint32_t bq16 = (uint32_t)((q8 & 1) << 4);
    const uint32_t brow = (uint32_t)(((q8 >> 1) * 8 + i8) * 128) + (uint32_t)(wn << 13);

    float acc[4][8][4];               // 128 regs
    #pragma unroll
    for (int a = 0; a < 4; a++)
        #pragma unroll
        for (int b = 0; b < 8; b++)
            #pragma unroll
            for (int c = 0; c < 4; c++) acc[a][b][c] = 0.f;

    // double-buffered fragment sets (ping-pong)
    uint32_t af[2][4][4];
    uint32_t bf[2][8][2];

    // ---- flat persistent mainloop, FIFO-aware ordering ----
    int buf = 0;
    #pragma unroll 1
    for (int q = 0; q < qtot; q++) {
        asm volatile("cp.async.wait_group 1;" ::: "memory");
        __syncthreads();

        const uint32_t stage = sbase + OFF_STAGE + buf * STAGE_BYTES;
        const uint32_t Arow = stage + arow;
        const uint32_t Brow = stage + A_BYTES + brow;

        // fragment batch loader for k-step j -> set s
        auto ldsm_step = [&](int j, int s) {
            const int kk = (j + kk0) & 3;
            const uint32_t cxA = ((uint32_t)(kk * 32) + aq16) ^ ix;
            const uint32_t cxB = ((uint32_t)(kk * 32) + bq16) ^ ix;
            #pragma unroll
            for (int mti = 0; mti < 4; mti++)
                ldsm4(af[s][mti][0], af[s][mti][1], af[s][mti][2], af[s][mti][3],
                      Arow + (uint32_t)(mti * 2048) + cxA);
            #pragma unroll
            for (int nt2 = 0; nt2 < 4; nt2++)
                ldsm4(bf[s][2 * nt2][0], bf[s][2 * nt2][1],
                      bf[s][2 * nt2 + 1][0], bf[s][2 * nt2 + 1][1],
                      Brow + (uint32_t)(nt2 * 2048) + cxB);
        };
        auto mma_step = [&](int s) {
            #pragma unroll
            for (int mti = 0; mti < 4; mti++)
                #pragma unroll
                for (int nti = 0; nti < 8; nti++)
                    mma_f16(acc[mti][nti],
                            af[s][mti][0], af[s][mti][1],
                            af[s][mti][2], af[s][mti][3],
                            bf[s][nti][0], bf[s][nti][1]);
        };

        // 1) LDSMs for k0,k1 FIRST (ahead of all prefetch wavefronts)
        ldsm_step(0, 0);
        ldsm_step(1, 1);

        // 2) prefetch traffic (drains under the MMA bursts below)
        if (q + 1 < qtot) stsA((buf == 2) ? 0 : buf + 1);
        if (q + 2 < qtot) {
            ldgA(q + 2);
            loadB(q + 2, (buf == 0) ? 2 : buf - 1);
            asm volatile("cp.async.commit_group;" ::: "memory");
        } else {
            asm volatile("cp.async.commit_group;" ::: "memory");
        }

        // 3) pipelined tail
        mma_step(0);
        ldsm_step(2, 0);
        mma_step(1);
        ldsm_step(3, 1);
        mma_step(0);
        mma_step(1);

        // ---- tile boundary: barrier-free inline epilogue (R13 form) ----
        if ((q & 3) == 3) {
            const int tile = bid + (q >> 2) * NCTA;
            const int g    = tile >> 6;
            const int m0   = (tile & 63) * MT;
            const int gb   = g * GOUT;

            const float* bp = bias + gb + wn * 64 + tig * 2;
            float2 bv[8];
            #pragma unroll
            for (int nti = 0; nti < 8; nti++)
                bv[nti] = *(const float2*)(bp + nti * 8);

            #pragma unroll
            for (int mti = 0; mti < 4; mti++) {
                const int row0 = m0 + wm * 64 + mti * 16 + grp;
                float* yr0 = y + (size_t)row0 * INF + gb + wn * 64 + tig * 2;
                float* yr1 = yr0 + (size_t)8 * INF;
                #pragma unroll
                for (int nti = 0; nti < 8; nti++) {
                    float2 v0, v1;
                    v0.x = acc[mti][nti][0] + bv[nti].x;
                    v0.y = acc[mti][nti][1] + bv[nti].y;
                    v1.x = acc[mti][nti][2] + bv[nti].x;
                    v1.y = acc[mti][nti][3] + bv[nti].y;
                    *(float2*)(yr0 + nti * 8) = v0;
                    *(float2*)(yr1 + nti * 8) = v1;
                    acc[mti][nti][0] = 0.f; acc[mti][nti][1] = 0.f;
                    acc[mti][nti][2] = 0.f; acc[mti][nti][3] = 0.f;
                }
            }
        }

        buf = (buf == 2) ? 0 : buf + 1;
    }
}

extern "C" void kernel_launch(void* const* d_in, const int* in_sizes, int n_in,
                              void* d_out, int out_size) {
    const float* x  = (const float*)d_in[0];
    const float* Wt = (const float*)d_in[1];
    const float* b  = (const float*)d_in[2];
    float* y = (float*)d_out;

    cudaFuncSetAttribute(GroupedLinear_35364760715975_kernel,
                         cudaFuncAttributeMaxDynamicSharedMemorySize, SMEM_TOTAL);

    // 1) convert W (1M f32) to fp16 rne (~1us)
    __half* wh_dev = nullptr;
    cudaGetSymbolAddress((void**)&wh_dev, g_Wh);
    GroupedLinear_cvtW_kernel<<<256, 256>>>((const float4*)Wt,
                                            (uint2*)wh_dev, NG * GOUT * GIN / 4);

    // 2) persistent fused cvt+GEMM: 152 CTAs (1 per SM on GB300)
    GroupedLinear_35364760715975_kernel<<<NCTA, NTHREADS, SMEM_TOTAL>>>(x, b, y);
}